// round 2
// baseline (speedup 1.0000x reference)
#include <cuda_runtime.h>
#include <cstdint>

#define NN 4096
#define DD 128
#define EPSF 1e-12f
#define BM 64
#define BK 16
#define KS 4

// Scratch (static device allocation — no cudaMalloc allowed)
__device__ float g_att[(size_t)NN * NN];   // 64 MB dense attention input
__device__ float g_feat[NN * DD];          // W @ activities
__device__ float g_norm[NN];               // row sums of g_att
__device__ int   g_is64;                   // index dtype sniff result

// ---------------------------------------------------------------------------
// Kernel 0: zero att + feat, and sniff whether index arrays are int64 or int32.
// For int64 values in [0,4096) every odd 32-bit word is 0; for int32 data the
// odd words are random indices (all-zero prob ~ (1/4096)^64).
// ---------------------------------------------------------------------------
__global__ void k_zero(const unsigned* __restrict__ cur_raw) {
    if (blockIdx.x == 0 && threadIdx.x == 0) {
        unsigned o = 0;
#pragma unroll
        for (int i = 1; i < 128; i += 2) o |= cur_raw[i];
        g_is64 = (o == 0) ? 1 : 0;
    }
    size_t idx    = (size_t)blockIdx.x * blockDim.x + threadIdx.x;
    size_t stride = (size_t)gridDim.x * blockDim.x;
    float4 z = make_float4(0.f, 0.f, 0.f, 0.f);
    float4* pa = (float4*)g_att;
    const size_t na = ((size_t)NN * NN) / 4;
    for (size_t i = idx; i < na; i += stride) pa[i] = z;
    float4* pf = (float4*)g_feat;
    const size_t nf = (size_t)(NN * DD) / 4;
    for (size_t i = idx; i < nf; i += stride) pf[i] = z;
}

// ---------------------------------------------------------------------------
// Kernel 1: one warp per edge. Each lane handles 4 of the 128 features via
// float4. dist = ||h + case - t||, val = exp(-dist), atomicAdd into att[t][c].
// cases stream (512 MB) is the dominant HBM traffic; activities gathers hit L2.
// ---------------------------------------------------------------------------
__global__ void k_edge(const void* __restrict__ curp, const void* __restrict__ tgtp,
                       const float* __restrict__ act, const float* __restrict__ cases,
                       int E) {
    int w = (int)((blockIdx.x * blockDim.x + threadIdx.x) >> 5);
    if (w >= E) return;
    int lane = threadIdx.x & 31;
    int c, t;
    if (g_is64) {
        c = (int)((const long long*)curp)[w];
        t = (int)((const long long*)tgtp)[w];
    } else {
        c = ((const int*)curp)[w];
        t = ((const int*)tgtp)[w];
    }
    float4 hv = ((const float4*)act)[(size_t)c * (DD / 4) + lane];
    float4 tv = ((const float4*)act)[(size_t)t * (DD / 4) + lane];
    float4 cv = ((const float4*)cases)[(size_t)w * (DD / 4) + lane];
    float dx = hv.x + cv.x - tv.x;
    float dy = hv.y + cv.y - tv.y;
    float dz = hv.z + cv.z - tv.z;
    float dw = hv.w + cv.w - tv.w;
    float s = dx * dx + dy * dy + dz * dz + dw * dw;
#pragma unroll
    for (int o = 16; o; o >>= 1) s += __shfl_xor_sync(0xffffffffu, s, o);
    if (lane == 0) {
        float v = __expf(-sqrtf(s));
        atomicAdd(&g_att[(size_t)t * NN + c], v);
    }
}

// ---------------------------------------------------------------------------
// Kernel 2: row sums of g_att -> g_norm. One block per row.
// ---------------------------------------------------------------------------
__global__ void k_rowsum() {
    int row = blockIdx.x;
    const float4* p = (const float4*)(g_att + (size_t)row * NN);
    float s = 0.f;
    for (int i = threadIdx.x; i < NN / 4; i += blockDim.x) {
        float4 v = p[i];
        s += (v.x + v.y) + (v.z + v.w);
    }
#pragma unroll
    for (int o = 16; o; o >>= 1) s += __shfl_xor_sync(0xffffffffu, s, o);
    __shared__ float red[8];
    int lane = threadIdx.x & 31, wid = threadIdx.x >> 5;
    if (lane == 0) red[wid] = s;
    __syncthreads();
    if (threadIdx.x < 8) {
        s = red[threadIdx.x];
        s += __shfl_xor_sync(0xffu, s, 4);
        s += __shfl_xor_sync(0xffu, s, 2);
        s += __shfl_xor_sync(0xffu, s, 1);
        if (threadIdx.x == 0) g_norm[row] = s;
    }
}

// ---------------------------------------------------------------------------
// Kernel 3: out = feat  (pre-init for GEMM2's "+ feat" term)
// ---------------------------------------------------------------------------
__global__ void k_copy(float* __restrict__ out) {
    int i = blockIdx.x * blockDim.x + threadIdx.x;
    float4* o = (float4*)out;
    const float4* f = (const float4*)g_feat;
    const int n = (NN * DD) / 4;
    for (int j = i; j < n; j += gridDim.x * blockDim.x) o[j] = f[j];
}

// ---------------------------------------------------------------------------
// Packed fp32 FMA (B300 FFMA2 — 2x fp32 throughput, PTX-only pattern)
// ---------------------------------------------------------------------------
__device__ __forceinline__ void fma2(unsigned long long& d, unsigned long long a,
                                     unsigned long long b) {
    asm volatile("fma.rn.f32x2 %0, %1, %2, %0;" : "+l"(d) : "l"(a), "l"(b));
}

// ---------------------------------------------------------------------------
// Kernel 4: shared GEMM, C[M=4096, D=128] = A[4096,4096] @ B[4096,128]
//   mode 0: A=W, B=activities, C=g_feat            (split-K atomic accumulate)
//   mode 1: A=g_att, B=g_feat, C=out (pre-set to feat), scaled by 1/(norm+eps)
// Tile: BM=64 x BN=128 x BK=16, 256 threads, 4x8 outputs/thread as 4x4 f32x2.
// Split-K=4 -> grid 256 blocks (covers 148 SMs).
// ---------------------------------------------------------------------------
__global__ void __launch_bounds__(256)
k_gemm(const float* __restrict__ Wp, const float* __restrict__ actp,
       float* __restrict__ outp, int mode) {
    __shared__ __align__(16) unsigned long long Ws2[BK][BM];  // {w,w} duplicated
    __shared__ __align__(16) float As[BK][DD];

    const float* A = mode ? g_att : Wp;
    const float* B = mode ? g_feat : actp;
    float* C       = mode ? outp  : g_feat;

    int tid = threadIdx.x;
    int tx = tid & 15;   // col group: cols tx*8 .. tx*8+7
    int ty = tid >> 4;   // row group: rows ty*4 .. ty*4+3
    int m0 = blockIdx.x * BM;
    int k0 = blockIdx.y * (NN / KS);

    unsigned long long acc[4][4];
#pragma unroll
    for (int i = 0; i < 4; i++)
#pragma unroll
        for (int j = 0; j < 4; j++) acc[i][j] = 0ull;

    int lr = tid >> 2, lq = tid & 3;   // A-tile load: row 0..63, float4 slot 0..3
    int ar = tid >> 4, ac = tid & 15;  // B-tile load: k-row 0..15, col4 group

    for (int kt = k0; kt < k0 + NN / KS; kt += BK) {
        float4 wv  = *(const float4*)(A + (size_t)(m0 + lr) * NN + kt + lq * 4);
        float4 av0 = *(const float4*)(B + (size_t)(kt + ar) * DD + ac * 4);
        float4 av1 = *(const float4*)(B + (size_t)(kt + ar) * DD + 64 + ac * 4);
        __syncthreads();
        {
            float wf[4] = {wv.x, wv.y, wv.z, wv.w};
#pragma unroll
            for (int j = 0; j < 4; j++) {
                unsigned long long p = (unsigned long long)__float_as_uint(wf[j]);
                Ws2[lq * 4 + j][lr] = p | (p << 32);
            }
            *(float4*)&As[ar][ac * 4]      = av0;
            *(float4*)&As[ar][64 + ac * 4] = av1;
        }
        __syncthreads();
#pragma unroll
        for (int kk = 0; kk < BK; kk++) {
            ulonglong2 t0 = *(const ulonglong2*)&Ws2[kk][ty * 4];
            ulonglong2 t1 = *(const ulonglong2*)&Ws2[kk][ty * 4 + 2];
            const ulonglong2* arow = (const ulonglong2*)&As[kk][0];
            ulonglong2 u0 = arow[tx * 2];
            ulonglong2 u1 = arow[tx * 2 + 1];
            unsigned long long w2[4] = {t0.x, t0.y, t1.x, t1.y};
            unsigned long long a2[4] = {u0.x, u0.y, u1.x, u1.y};
#pragma unroll
            for (int i = 0; i < 4; i++)
#pragma unroll
                for (int j = 0; j < 4; j++) fma2(acc[i][j], w2[i], a2[j]);
        }
    }

    if (mode == 0) {
#pragma unroll
        for (int i = 0; i < 4; i++) {
            int row = m0 + ty * 4 + i;
#pragma unroll
            for (int j = 0; j < 4; j++) {
                int col = tx * 8 + j * 2;
                unsigned long long v = acc[i][j];
                atomicAdd(&C[(size_t)row * DD + col],     __uint_as_float((unsigned)v));
                atomicAdd(&C[(size_t)row * DD + col + 1], __uint_as_float((unsigned)(v >> 32)));
            }
        }
    } else {
#pragma unroll
        for (int i = 0; i < 4; i++) {
            int row = m0 + ty * 4 + i;
            float inv = 1.0f / (g_norm[row] + EPSF);
#pragma unroll
            for (int j = 0; j < 4; j++) {
                int col = tx * 8 + j * 2;
                unsigned long long v = acc[i][j];
                atomicAdd(&C[(size_t)row * DD + col],     inv * __uint_as_float((unsigned)v));
                atomicAdd(&C[(size_t)row * DD + col + 1], inv * __uint_as_float((unsigned)(v >> 32)));
            }
        }
    }
}

// ---------------------------------------------------------------------------
extern "C" void kernel_launch(void* const* d_in, const int* in_sizes, int n_in,
                              void* d_out, int out_size) {
    const void*  cur   = d_in[0];                 // currents (int64 or int32), [E]
    const void*  tgt   = d_in[1];                 // targets, [E]
    const float* act   = (const float*)d_in[2];   // activities_features [N, D]
    const float* cases = (const float*)d_in[3];   // cases_features [E, D]
    const float* W     = (const float*)d_in[4];   // W [N, N]
    float* out = (float*)d_out;                   // h [N, D]

    int E = in_sizes[3] / DD;                     // unambiguous regardless of index dtype

    // 0) zero scratch + dtype sniff
    k_zero<<<4096, 256>>>((const unsigned*)cur);
    // 1) edge scatter into dense att
    k_edge<<<(E + 7) / 8, 256>>>(cur, tgt, act, cases, E);
    // 2) feat = W @ activities (split-K accumulate into zeroed g_feat)
    k_gemm<<<dim3(NN / BM, KS), 256>>>(W, act, out, 0);
    // 3) row sums of att
    k_rowsum<<<NN, 256>>>();
    // 4) out = feat
    k_copy<<<512, 256>>>(out);
    // 5) out += (att @ feat) / (norm + eps)
    k_gemm<<<dim3(NN / BM, KS), 256>>>(W, act, out, 1);
}

// round 3
// speedup vs baseline: 1.8809x; 1.8809x over previous
#include <cuda_runtime.h>
#include <cstdint>

#define NN 4096
#define DD 128
#define EPSF 1e-12f
#define KS 4            // split-K factor for GEMMs
#define BM 128          // GEMM block rows
#define BK 16           // GEMM k-tile
#define AS_STRIDE 20    // floats; conflict-free for As[m][k] frag reads
#define BS_STRIDE 136   // floats; conflict-free for Bs[k][n] frag reads

// Scratch (static device allocation — no cudaMalloc allowed)
__device__ float g_att[(size_t)NN * NN];   // 64 MB dense attention input
__device__ float g_feat[NN * DD];          // W @ activities
__device__ float g_norm[NN];               // row sums of g_att
__device__ int   g_is64;                   // index dtype sniff result

// ---------------------------------------------------------------------------
// Kernel 0: zero att + feat + norm, sniff int64 vs int32 indices.
// ---------------------------------------------------------------------------
__global__ void k_zero(const unsigned* __restrict__ cur_raw) {
    if (blockIdx.x == 0 && threadIdx.x == 0) {
        unsigned o = 0;
#pragma unroll
        for (int i = 1; i < 128; i += 2) o |= cur_raw[i];
        g_is64 = (o == 0) ? 1 : 0;
    }
    size_t idx    = (size_t)blockIdx.x * blockDim.x + threadIdx.x;
    size_t stride = (size_t)gridDim.x * blockDim.x;
    float4 z = make_float4(0.f, 0.f, 0.f, 0.f);
    float4* pa = (float4*)g_att;
    const size_t na = ((size_t)NN * NN) / 4;
    for (size_t i = idx; i < na; i += stride) pa[i] = z;
    float4* pf = (float4*)g_feat;
    const size_t nf = (size_t)(NN * DD) / 4;
    for (size_t i = idx; i < nf; i += stride) pf[i] = z;
    for (size_t i = idx; i < NN; i += stride) g_norm[i] = 0.f;
}

// ---------------------------------------------------------------------------
// Kernel 1: one warp per edge. dist = ||h + case - t||, val = exp(-dist),
// scatter into att[t][c] AND accumulate row norm (linear => == row sums).
// ---------------------------------------------------------------------------
__global__ void k_edge(const void* __restrict__ curp, const void* __restrict__ tgtp,
                       const float* __restrict__ act, const float* __restrict__ cases,
                       int E) {
    int w = (int)((blockIdx.x * blockDim.x + threadIdx.x) >> 5);
    if (w >= E) return;
    int lane = threadIdx.x & 31;
    int c, t;
    if (g_is64) {
        c = (int)((const long long*)curp)[w];
        t = (int)((const long long*)tgtp)[w];
    } else {
        c = ((const int*)curp)[w];
        t = ((const int*)tgtp)[w];
    }
    float4 hv = ((const float4*)act)[(size_t)c * (DD / 4) + lane];
    float4 tv = ((const float4*)act)[(size_t)t * (DD / 4) + lane];
    float4 cv = __ldcs(((const float4*)cases) + (size_t)w * (DD / 4) + lane);
    float dx = hv.x + cv.x - tv.x;
    float dy = hv.y + cv.y - tv.y;
    float dz = hv.z + cv.z - tv.z;
    float dw = hv.w + cv.w - tv.w;
    float s = dx * dx + dy * dy + dz * dz + dw * dw;
#pragma unroll
    for (int o = 16; o; o >>= 1) s += __shfl_xor_sync(0xffffffffu, s, o);
    if (lane == 0) {
        float v = __expf(-sqrtf(s));
        atomicAdd(&g_att[(size_t)t * NN + c], v);
        atomicAdd(&g_norm[t], v);
    }
}

// ---------------------------------------------------------------------------
// Kernel 3: out = feat  (pre-init for GEMM2's "+ feat" term)
// ---------------------------------------------------------------------------
__global__ void k_copy(float* __restrict__ out) {
    int i = blockIdx.x * blockDim.x + threadIdx.x;
    float4* o = (float4*)out;
    const float4* f = (const float4*)g_feat;
    const int n = (NN * DD) / 4;
    for (int j = i; j < n; j += gridDim.x * blockDim.x) o[j] = f[j];
}

// ---------------------------------------------------------------------------
// Tensor-core helpers
// ---------------------------------------------------------------------------
__device__ __forceinline__ unsigned f2tf(float x) {
    unsigned r;
    asm("cvt.rna.tf32.f32 %0, %1;" : "=r"(r) : "f"(x));
    return r;
}

__device__ __forceinline__ void mma8(float* c, unsigned a0, unsigned a1,
                                     unsigned a2, unsigned a3,
                                     unsigned b0, unsigned b1) {
    asm volatile(
        "mma.sync.aligned.m16n8k8.row.col.f32.tf32.tf32.f32 "
        "{%0,%1,%2,%3}, {%4,%5,%6,%7}, {%8,%9}, {%0,%1,%2,%3};"
        : "+f"(c[0]), "+f"(c[1]), "+f"(c[2]), "+f"(c[3])
        : "r"(a0), "r"(a1), "r"(a2), "r"(a3), "r"(b0), "r"(b1));
}

__device__ __forceinline__ void cp16(float* smem_dst, const float* gmem_src) {
    unsigned sa = (unsigned)__cvta_generic_to_shared(smem_dst);
    asm volatile("cp.async.cg.shared.global [%0], [%1], 16;" :: "r"(sa), "l"(gmem_src));
}

// ---------------------------------------------------------------------------
// Kernel 4: tensor-core GEMM  C[4096,128] = A[4096,4096] @ B[4096,128]
// tf32 mma.sync m16n8k8 with 3-term precision compensation:
//   C += Ah*Bh + Al*Bh + Ah*Bl   (error ~2^-22, fp32-like)
// 256 threads = 8 warps (4 along M x 2 along N), warp tile 32x64.
// Double-buffered cp.async BK=16 tiles. Split-K=4 with atomic epilogue.
//   mode 0: A=W,     B=activities, C=g_feat (zeroed)
//   mode 1: A=g_att, B=g_feat,     C=out (pre-set to feat), scale 1/(norm+eps)
// ---------------------------------------------------------------------------
__global__ void __launch_bounds__(256)
k_gemm_tc(const float* __restrict__ Wp, const float* __restrict__ actp,
          float* __restrict__ outp, int mode) {
    __shared__ __align__(16) float As[2][BM * AS_STRIDE];  // 20480 B
    __shared__ __align__(16) float Bs[2][BK * BS_STRIDE];  // 17408 B

    const float* A = mode ? g_att : Wp;
    const float* B = mode ? g_feat : actp;
    float* C       = mode ? outp   : g_feat;

    const int tid  = threadIdx.x;
    const int lane = tid & 31;
    const int w    = tid >> 5;
    const int wm   = w & 3;      // warp row group (0..3) -> rows wm*32..+32
    const int wn   = w >> 2;     // warp col group (0..1) -> cols wn*64..+64
    const int m0   = blockIdx.x * BM;
    const int k0   = blockIdx.y * (NN / KS);
    const int NT   = (NN / KS) / BK;  // 64 k-tiles

    float acc[2][8][4];
#pragma unroll
    for (int t = 0; t < 2; t++)
#pragma unroll
        for (int j = 0; j < 8; j++)
#pragma unroll
            for (int q = 0; q < 4; q++) acc[t][j][q] = 0.f;

    // ---- tile loader (cp.async, 4 x 16B per thread) ----
    auto load_tile = [&](int buf, int kt) {
#pragma unroll
        for (int s = 0; s < 2; s++) {
            int chunk = tid + 256 * s;              // 0..511
            int row = chunk >> 2, kq = chunk & 3;   // A: 128 rows x 4 float4
            cp16(&As[buf][row * AS_STRIDE + kq * 4],
                 A + (size_t)(m0 + row) * NN + kt + kq * 4);
        }
#pragma unroll
        for (int s = 0; s < 2; s++) {
            int chunk = tid + 256 * s;
            int kr = chunk >> 5, nq = chunk & 31;   // B: 16 rows x 32 float4
            cp16(&Bs[buf][kr * BS_STRIDE + nq * 4],
                 B + (size_t)(kt + kr) * DD + nq * 4);
        }
        asm volatile("cp.async.commit_group;");
    };

    load_tile(0, k0);

    for (int it = 0; it < NT; it++) {
        int buf = it & 1;
        if (it + 1 < NT) {
            load_tile(buf ^ 1, k0 + (it + 1) * BK);
            asm volatile("cp.async.wait_group 1;");
        } else {
            asm volatile("cp.async.wait_group 0;");
        }
        __syncthreads();

#pragma unroll
        for (int ks = 0; ks < BK; ks += 8) {
            // A fragments (m16k8): hi/lo split
            unsigned ah[2][4], al[2][4];
#pragma unroll
            for (int t = 0; t < 2; t++) {
                int r = wm * 32 + t * 16 + (lane >> 2);
                int c = ks + (lane & 3);
                float x0 = As[buf][r * AS_STRIDE + c];
                float x1 = As[buf][(r + 8) * AS_STRIDE + c];
                float x2 = As[buf][r * AS_STRIDE + c + 4];
                float x3 = As[buf][(r + 8) * AS_STRIDE + c + 4];
                ah[t][0] = f2tf(x0); al[t][0] = __float_as_uint(x0 - __uint_as_float(ah[t][0]));
                ah[t][1] = f2tf(x1); al[t][1] = __float_as_uint(x1 - __uint_as_float(ah[t][1]));
                ah[t][2] = f2tf(x2); al[t][2] = __float_as_uint(x2 - __uint_as_float(ah[t][2]));
                ah[t][3] = f2tf(x3); al[t][3] = __float_as_uint(x3 - __uint_as_float(ah[t][3]));
            }
            // process ntiles in halves of 4 to bound register pressure
#pragma unroll
            for (int jb = 0; jb < 2; jb++) {
                unsigned bh[4][2], bl[4][2];
#pragma unroll
                for (int jj = 0; jj < 4; jj++) {
                    int j = jb * 4 + jj;
                    int kk = ks + (lane & 3);
                    int n  = wn * 64 + j * 8 + (lane >> 2);
                    float y0 = Bs[buf][kk * BS_STRIDE + n];
                    float y1 = Bs[buf][(kk + 4) * BS_STRIDE + n];
                    bh[jj][0] = f2tf(y0); bl[jj][0] = __float_as_uint(y0 - __uint_as_float(bh[jj][0]));
                    bh[jj][1] = f2tf(y1); bl[jj][1] = __float_as_uint(y1 - __uint_as_float(bh[jj][1]));
                }
#pragma unroll
                for (int t = 0; t < 2; t++)
#pragma unroll
                    for (int jj = 0; jj < 4; jj++) {
                        float* cc = acc[t][jb * 4 + jj];
                        mma8(cc, ah[t][0], ah[t][1], ah[t][2], ah[t][3], bh[jj][0], bh[jj][1]);
                        mma8(cc, al[t][0], al[t][1], al[t][2], al[t][3], bh[jj][0], bh[jj][1]);
                        mma8(cc, ah[t][0], ah[t][1], ah[t][2], ah[t][3], bl[jj][0], bl[jj][1]);
                    }
            }
        }
        __syncthreads();
    }

    // ---- epilogue: split-K atomic accumulate (mode1 scales by 1/(norm+eps)) ----
#pragma unroll
    for (int t = 0; t < 2; t++) {
        int r0 = m0 + wm * 32 + t * 16 + (lane >> 2);
        float inv0 = 1.f, inv1 = 1.f;
        if (mode) {
            inv0 = 1.f / (g_norm[r0] + EPSF);
            inv1 = 1.f / (g_norm[r0 + 8] + EPSF);
        }
#pragma unroll
        for (int j = 0; j < 8; j++) {
            int cc = wn * 64 + j * 8 + (lane & 3) * 2;
            atomicAdd(&C[(size_t)r0 * DD + cc],           inv0 * acc[t][j][0]);
            atomicAdd(&C[(size_t)r0 * DD + cc + 1],       inv0 * acc[t][j][1]);
            atomicAdd(&C[(size_t)(r0 + 8) * DD + cc],     inv1 * acc[t][j][2]);
            atomicAdd(&C[(size_t)(r0 + 8) * DD + cc + 1], inv1 * acc[t][j][3]);
        }
    }
}

// ---------------------------------------------------------------------------
extern "C" void kernel_launch(void* const* d_in, const int* in_sizes, int n_in,
                              void* d_out, int out_size) {
    const void*  cur   = d_in[0];                 // currents (int64 or int32), [E]
    const void*  tgt   = d_in[1];                 // targets, [E]
    const float* act   = (const float*)d_in[2];   // activities_features [N, D]
    const float* cases = (const float*)d_in[3];   // cases_features [E, D]
    const float* W     = (const float*)d_in[4];   // W [N, N]
    float* out = (float*)d_out;                   // h [N, D]

    int E = in_sizes[3] / DD;                     // unambiguous regardless of index dtype

    // 0) zero scratch + dtype sniff
    k_zero<<<4096, 256>>>((const unsigned*)cur);
    // 1) edge scatter into dense att + row norms
    k_edge<<<(E + 7) / 8, 256>>>(cur, tgt, act, cases, E);
    // 2) feat = W @ activities (split-K accumulate into zeroed g_feat)
    k_gemm_tc<<<dim3(NN / BM, KS), 256>>>(W, act, out, 0);
    // 3) out = feat
    k_copy<<<512, 256>>>(out);
    // 4) out += (att @ feat) / (norm + eps)
    k_gemm_tc<<<dim3(NN / BM, KS), 256>>>(W, act, out, 1);
}

// round 5
// speedup vs baseline: 2.3174x; 1.2321x over previous
#include <cuda_runtime.h>
#include <cstdint>

#define NN 4096
#define DD 128
#define EPSF 1e-12f
#define KS 4            // split-K factor for GEMMs
#define BM 128          // GEMM block rows
#define BK 16           // GEMM k-tile
#define AS_STRIDE 20    // floats; conflict-free for As[m][k] frag reads
#define BS_STRIDE 136   // floats; conflict-free for Bs[k][n] frag reads

// Scratch (static device allocation — no cudaMalloc allowed)
__device__ float g_att[(size_t)NN * NN];   // 64 MB dense attention input
__device__ float g_feat[NN * DD];          // W @ activities
__device__ float g_norm[NN];               // row sums of g_att
__device__ int   g_is64;                   // index dtype sniff result

// ---------------------------------------------------------------------------
// Kernel 0: zero att + feat + norm, sniff int64 vs int32 indices.
// ---------------------------------------------------------------------------
__global__ void k_zero(const unsigned* __restrict__ cur_raw) {
    if (blockIdx.x == 0 && threadIdx.x == 0) {
        unsigned o = 0;
#pragma unroll
        for (int i = 1; i < 128; i += 2) o |= cur_raw[i];
        g_is64 = (o == 0) ? 1 : 0;
    }
    size_t idx    = (size_t)blockIdx.x * blockDim.x + threadIdx.x;
    size_t stride = (size_t)gridDim.x * blockDim.x;
    float4 z = make_float4(0.f, 0.f, 0.f, 0.f);
    float4* pa = (float4*)g_att;
    const size_t na = ((size_t)NN * NN) / 4;
    for (size_t i = idx; i < na; i += stride) pa[i] = z;
    float4* pf = (float4*)g_feat;
    const size_t nf = (size_t)(NN * DD) / 4;
    for (size_t i = idx; i < nf; i += stride) pf[i] = z;
    for (size_t i = idx; i < NN; i += stride) g_norm[i] = 0.f;
}

// ---------------------------------------------------------------------------
// Kernel 1: one warp per edge. dist = ||h + case - t||, val = exp(-dist),
// scatter into att[t][c] and accumulate row norm (linear => == row sums).
// ---------------------------------------------------------------------------
__global__ void k_edge(const void* __restrict__ curp, const void* __restrict__ tgtp,
                       const float* __restrict__ act, const float* __restrict__ cases,
                       int E) {
    int w = (int)((blockIdx.x * blockDim.x + threadIdx.x) >> 5);
    if (w >= E) return;
    int lane = threadIdx.x & 31;
    int c, t;
    if (g_is64) {
        c = (int)((const long long*)curp)[w];
        t = (int)((const long long*)tgtp)[w];
    } else {
        c = ((const int*)curp)[w];
        t = ((const int*)tgtp)[w];
    }
    float4 hv = ((const float4*)act)[(size_t)c * (DD / 4) + lane];
    float4 tv = ((const float4*)act)[(size_t)t * (DD / 4) + lane];
    float4 cv = __ldcs(((const float4*)cases) + (size_t)w * (DD / 4) + lane);
    float dx = hv.x + cv.x - tv.x;
    float dy = hv.y + cv.y - tv.y;
    float dz = hv.z + cv.z - tv.z;
    float dw = hv.w + cv.w - tv.w;
    float s = dx * dx + dy * dy + dz * dz + dw * dw;
#pragma unroll
    for (int o = 16; o; o >>= 1) s += __shfl_xor_sync(0xffffffffu, s, o);
    if (lane == 0) {
        float v = __expf(-sqrtf(s));
        atomicAdd(&g_att[(size_t)t * NN + c], v);
        atomicAdd(&g_norm[t], v);
    }
}

// ---------------------------------------------------------------------------
// Kernel 3: out = feat  (pre-init for GEMM2's "+ feat" term)
// ---------------------------------------------------------------------------
__global__ void k_copy(float* __restrict__ out) {
    int i = blockIdx.x * blockDim.x + threadIdx.x;
    float4* o = (float4*)out;
    const float4* f = (const float4*)g_feat;
    const int n = (NN * DD) / 4;
    for (int j = i; j < n; j += gridDim.x * blockDim.x) o[j] = f[j];
}

// ---------------------------------------------------------------------------
// Tensor-core helpers (legacy mma.sync path — compute_103-safe)
// ---------------------------------------------------------------------------
__device__ __forceinline__ unsigned f2tf(float x) {
    unsigned r;
    asm("cvt.rna.tf32.f32 %0, %1;" : "=r"(r) : "f"(x));
    return r;
}

__device__ __forceinline__ void mma8(float* c, unsigned a0, unsigned a1,
                                     unsigned a2, unsigned a3,
                                     unsigned b0, unsigned b1) {
    asm volatile(
        "mma.sync.aligned.m16n8k8.row.col.f32.tf32.tf32.f32 "
        "{%0,%1,%2,%3}, {%4,%5,%6,%7}, {%8,%9}, {%0,%1,%2,%3};"
        : "+f"(c[0]), "+f"(c[1]), "+f"(c[2]), "+f"(c[3])
        : "r"(a0), "r"(a1), "r"(a2), "r"(a3), "r"(b0), "r"(b1));
}

__device__ __forceinline__ void cp16(float* smem_dst, const float* gmem_src) {
    unsigned sa = (unsigned)__cvta_generic_to_shared(smem_dst);
    asm volatile("cp.async.cg.shared.global [%0], [%1], 16;" :: "r"(sa), "l"(gmem_src));
}

// ---------------------------------------------------------------------------
// Kernel 4: tensor-core GEMM  C[4096,128] = A[4096,4096] @ B[4096,128]
// Pure tf32 (1-term): aggregate rel err ~2-4e-4, under the 1e-3 threshold.
// 256 threads = 8 warps (4 along M x 2 along N), warp tile 32x64.
// Double-buffered cp.async BK=16 tiles. Split-K=4 with atomic epilogue.
//   mode 0: A=W,     B=activities, C=g_feat (zeroed)
//   mode 1: A=g_att, B=g_feat,     C=out (pre-set to feat), scale 1/(norm+eps)
// ---------------------------------------------------------------------------
__global__ void __launch_bounds__(256)
k_gemm_tc(const float* __restrict__ Wp, const float* __restrict__ actp,
          float* __restrict__ outp, int mode) {
    __shared__ __align__(16) float As[2][BM * AS_STRIDE];  // 20480 B
    __shared__ __align__(16) float Bs[2][BK * BS_STRIDE];  // 17408 B

    const float* A = mode ? g_att : Wp;
    const float* B = mode ? g_feat : actp;
    float* C       = mode ? outp   : g_feat;

    const int tid  = threadIdx.x;
    const int lane = tid & 31;
    const int w    = tid >> 5;
    const int wm   = w & 3;      // warp row group (0..3) -> rows wm*32..+32
    const int wn   = w >> 2;     // warp col group (0..1) -> cols wn*64..+64
    const int m0   = blockIdx.x * BM;
    const int k0   = blockIdx.y * (NN / KS);
    const int NT   = (NN / KS) / BK;  // 64 k-tiles

    float acc[2][8][4];
#pragma unroll
    for (int t = 0; t < 2; t++)
#pragma unroll
        for (int j = 0; j < 8; j++)
#pragma unroll
            for (int q = 0; q < 4; q++) acc[t][j][q] = 0.f;

    // ---- tile loader (cp.async, 4 x 16B per thread) ----
    auto load_tile = [&](int buf, int kt) {
#pragma unroll
        for (int s = 0; s < 2; s++) {
            int chunk = tid + 256 * s;              // 0..511
            int row = chunk >> 2, kq = chunk & 3;   // A: 128 rows x 4 float4
            cp16(&As[buf][row * AS_STRIDE + kq * 4],
                 A + (size_t)(m0 + row) * NN + kt + kq * 4);
        }
#pragma unroll
        for (int s = 0; s < 2; s++) {
            int chunk = tid + 256 * s;
            int kr = chunk >> 5, nq = chunk & 31;   // B: 16 rows x 32 float4
            cp16(&Bs[buf][kr * BS_STRIDE + nq * 4],
                 B + (size_t)(kt + kr) * DD + nq * 4);
        }
        asm volatile("cp.async.commit_group;");
    };

    load_tile(0, k0);

    for (int it = 0; it < NT; it++) {
        int buf = it & 1;
        if (it + 1 < NT) {
            load_tile(buf ^ 1, k0 + (it + 1) * BK);
            asm volatile("cp.async.wait_group 1;");
        } else {
            asm volatile("cp.async.wait_group 0;");
        }
        __syncthreads();

#pragma unroll
        for (int ks = 0; ks < BK; ks += 8) {
            // A fragments (m16k8), tf32-converted
            unsigned ah[2][4];
#pragma unroll
            for (int t = 0; t < 2; t++) {
                int r = wm * 32 + t * 16 + (lane >> 2);
                int c = ks + (lane & 3);
                ah[t][0] = f2tf(As[buf][r * AS_STRIDE + c]);
                ah[t][1] = f2tf(As[buf][(r + 8) * AS_STRIDE + c]);
                ah[t][2] = f2tf(As[buf][r * AS_STRIDE + c + 4]);
                ah[t][3] = f2tf(As[buf][(r + 8) * AS_STRIDE + c + 4]);
            }
#pragma unroll
            for (int jb = 0; jb < 2; jb++) {
                unsigned bh[4][2];
#pragma unroll
                for (int jj = 0; jj < 4; jj++) {
                    int j = jb * 4 + jj;
                    int kk = ks + (lane & 3);
                    int n  = wn * 64 + j * 8 + (lane >> 2);
                    bh[jj][0] = f2tf(Bs[buf][kk * BS_STRIDE + n]);
                    bh[jj][1] = f2tf(Bs[buf][(kk + 4) * BS_STRIDE + n]);
                }
#pragma unroll
                for (int t = 0; t < 2; t++)
#pragma unroll
                    for (int jj = 0; jj < 4; jj++) {
                        mma8(acc[t][jb * 4 + jj], ah[t][0], ah[t][1], ah[t][2],
                             ah[t][3], bh[jj][0], bh[jj][1]);
                    }
            }
        }
        __syncthreads();
    }

    // ---- epilogue: split-K atomic accumulate (mode1 scales by 1/(norm+eps)) ----
#pragma unroll
    for (int t = 0; t < 2; t++) {
        int r0 = m0 + wm * 32 + t * 16 + (lane >> 2);
        float inv0 = 1.f, inv1 = 1.f;
        if (mode) {
            inv0 = 1.f / (g_norm[r0] + EPSF);
            inv1 = 1.f / (g_norm[r0 + 8] + EPSF);
        }
#pragma unroll
        for (int j = 0; j < 8; j++) {
            int cc = wn * 64 + j * 8 + (lane & 3) * 2;
            atomicAdd(&C[(size_t)r0 * DD + cc],           inv0 * acc[t][j][0]);
            atomicAdd(&C[(size_t)r0 * DD + cc + 1],       inv0 * acc[t][j][1]);
            atomicAdd(&C[(size_t)(r0 + 8) * DD + cc],     inv1 * acc[t][j][2]);
            atomicAdd(&C[(size_t)(r0 + 8) * DD + cc + 1], inv1 * acc[t][j][3]);
        }
    }
}

// ---------------------------------------------------------------------------
extern "C" void kernel_launch(void* const* d_in, const int* in_sizes, int n_in,
                              void* d_out, int out_size) {
    const void*  cur   = d_in[0];                 // currents (int64 or int32), [E]
    const void*  tgt   = d_in[1];                 // targets, [E]
    const float* act   = (const float*)d_in[2];   // activities_features [N, D]
    const float* cases = (const float*)d_in[3];   // cases_features [E, D]
    const float* W     = (const float*)d_in[4];   // W [N, N]
    float* out = (float*)d_out;                   // h [N, D]

    int E = in_sizes[3] / DD;                     // unambiguous regardless of index dtype

    // 0) zero scratch + dtype sniff
    k_zero<<<4096, 256>>>((const unsigned*)cur);
    // 1) edge scatter into dense att + row norms
    k_edge<<<(E + 7) / 8, 256>>>(cur, tgt, act, cases, E);
    // 2) feat = W @ activities (split-K accumulate into zeroed g_feat)
    k_gemm_tc<<<dim3(NN / BM, KS), 256>>>(W, act, out, 0);
    // 3) out = feat
    k_copy<<<512, 256>>>(out);
    // 4) out += (att @ feat) / (norm + eps)
    k_gemm_tc<<<dim3(NN / BM, KS), 256>>>(W, act, out, 1);
}

// round 8
// speedup vs baseline: 2.4336x; 1.0502x over previous
#include <cuda_runtime.h>
#include <cstdint>

#define NN 4096
#define DD 128
#define EPSF 1e-12f
#define KS 8            // split-K factor for GEMMs (256 CTAs -> 2/SM)
#define BM 128          // GEMM block rows
#define BK 16           // GEMM k-tile
#define AS_STRIDE 20    // floats; conflict-free for As[m][k] frag reads
#define BS_STRIDE 136   // floats; conflict-free for Bs[k][n] frag reads

// Scratch (static device allocation — no cudaMalloc allowed)
__device__ __align__(256) float g_att[(size_t)NN * NN];  // 64 MB dense att input
__device__ __align__(256) float g_feat[NN * DD];         // W @ activities
__device__ __align__(256) float g_norm[NN];              // row sums of g_att
__device__ int g_is64;                                   // index dtype sniff

// ---------------------------------------------------------------------------
// Kernel 0: zero att + feat + norm, sniff int64 vs int32 indices.
// ---------------------------------------------------------------------------
__global__ void k_zero(const unsigned* __restrict__ cur_raw) {
    if (blockIdx.x == 0 && threadIdx.x == 0) {
        unsigned o = 0;
#pragma unroll
        for (int i = 1; i < 128; i += 2) o |= cur_raw[i];
        g_is64 = (o == 0) ? 1 : 0;
    }
    size_t idx    = (size_t)blockIdx.x * blockDim.x + threadIdx.x;
    size_t stride = (size_t)gridDim.x * blockDim.x;
    float4 z = make_float4(0.f, 0.f, 0.f, 0.f);
    float4* pa = (float4*)g_att;
    const size_t na = ((size_t)NN * NN) / 4;
    for (size_t i = idx; i < na; i += stride) pa[i] = z;
    float4* pf = (float4*)g_feat;
    const size_t nf = (size_t)(NN * DD) / 4;
    for (size_t i = idx; i < nf; i += stride) pf[i] = z;
    for (size_t i = idx; i < NN; i += stride) g_norm[i] = 0.f;
}

// ---------------------------------------------------------------------------
// Kernel 1: one warp per edge. dist = ||h + case - t||, val = exp(-dist),
// scatter into att[t][c] and accumulate row norm (linear => == row sums).
// ---------------------------------------------------------------------------
__global__ void k_edge(const void* __restrict__ curp, const void* __restrict__ tgtp,
                       const float* __restrict__ act, const float* __restrict__ cases,
                       int E) {
    int w = (int)((blockIdx.x * blockDim.x + threadIdx.x) >> 5);
    if (w >= E) return;
    int lane = threadIdx.x & 31;
    int c, t;
    if (g_is64) {
        c = (int)((const long long*)curp)[w];
        t = (int)((const long long*)tgtp)[w];
    } else {
        c = ((const int*)curp)[w];
        t = ((const int*)tgtp)[w];
    }
    float4 hv = ((const float4*)act)[(size_t)c * (DD / 4) + lane];
    float4 tv = ((const float4*)act)[(size_t)t * (DD / 4) + lane];
    float4 cv = __ldcs(((const float4*)cases) + (size_t)w * (DD / 4) + lane);
    float dx = hv.x + cv.x - tv.x;
    float dy = hv.y + cv.y - tv.y;
    float dz = hv.z + cv.z - tv.z;
    float dw = hv.w + cv.w - tv.w;
    float s = dx * dx + dy * dy + dz * dz + dw * dw;
#pragma unroll
    for (int o = 16; o; o >>= 1) s += __shfl_xor_sync(0xffffffffu, s, o);
    if (lane == 0) {
        float v = __expf(-sqrtf(s));
        atomicAdd(&g_att[(size_t)t * NN + c], v);
        atomicAdd(&g_norm[t], v);
    }
}

// ---------------------------------------------------------------------------
// Kernel 3: out = feat  (pre-init for GEMM2's "+ feat" term)
// ---------------------------------------------------------------------------
__global__ void k_copy(float* __restrict__ out) {
    int i = blockIdx.x * blockDim.x + threadIdx.x;
    float4* o = (float4*)out;
    const float4* f = (const float4*)g_feat;
    const int n = (NN * DD) / 4;
    for (int j = i; j < n; j += gridDim.x * blockDim.x) o[j] = f[j];
}

// ---------------------------------------------------------------------------
// Tensor-core helpers (legacy mma.sync path — compute_103-safe)
// ---------------------------------------------------------------------------
__device__ __forceinline__ unsigned f2tf(float x) {
    unsigned r;
    asm("cvt.rna.tf32.f32 %0, %1;" : "=r"(r) : "f"(x));
    return r;
}

__device__ __forceinline__ void mma8(float* c, unsigned a0, unsigned a1,
                                     unsigned a2, unsigned a3,
                                     unsigned b0, unsigned b1) {
    asm volatile(
        "mma.sync.aligned.m16n8k8.row.col.f32.tf32.tf32.f32 "
        "{%0,%1,%2,%3}, {%4,%5,%6,%7}, {%8,%9}, {%0,%1,%2,%3};"
        : "+f"(c[0]), "+f"(c[1]), "+f"(c[2]), "+f"(c[3])
        : "r"(a0), "r"(a1), "r"(a2), "r"(a3), "r"(b0), "r"(b1));
}

__device__ __forceinline__ void cp16(float* smem_dst, const float* gmem_src) {
    unsigned sa = (unsigned)__cvta_generic_to_shared(smem_dst);
    asm volatile("cp.async.cg.shared.global [%0], [%1], 16;" :: "r"(sa), "l"(gmem_src));
}

// ---------------------------------------------------------------------------
// Kernel 4: tensor-core GEMM  C[4096,128] = A[4096,4096] @ B[4096,128]
// Pure tf32 (1-term): aggregate rel err ~3e-4, under the 1e-3 threshold.
// 256 threads = 8 warps (4 along M x 2 along N), warp tile 32x64.
// Double-buffered cp.async BK=16 tiles. Split-K=8 with atomic epilogue.
// __launch_bounds__(256,2): cap regs at 128 so 2 CTAs/SM co-reside
// (the loop is latency-exposed, not issue-bound — occupancy hides it).
//   mode 0: A=W,     B=activities, C=g_feat (zeroed)
//   mode 1: A=g_att, B=g_feat,     C=out (pre-set to feat), scale 1/(norm+eps)
// ---------------------------------------------------------------------------
__global__ void __launch_bounds__(256, 2)
k_gemm_tc(const float* __restrict__ Wp, const float* __restrict__ actp,
          float* __restrict__ outp, int mode) {
    __shared__ __align__(16) float As[2][BM * AS_STRIDE];  // 20480 B
    __shared__ __align__(16) float Bs[2][BK * BS_STRIDE];  // 17408 B

    const float* A = mode ? g_att : Wp;
    const float* B = mode ? g_feat : actp;
    float* C       = mode ? outp   : g_feat;

    const int tid  = threadIdx.x;
    const int lane = tid & 31;
    const int w    = tid >> 5;
    const int wm   = w & 3;      // warp row group (0..3) -> rows wm*32..+32
    const int wn   = w >> 2;     // warp col group (0..1) -> cols wn*64..+64
    const int m0   = blockIdx.x * BM;
    const int k0   = blockIdx.y * (NN / KS);
    const int NT   = (NN / KS) / BK;  // 32 k-tiles

    float acc[2][8][4];
#pragma unroll
    for (int t = 0; t < 2; t++)
#pragma unroll
        for (int j = 0; j < 8; j++)
#pragma unroll
            for (int q = 0; q < 4; q++) acc[t][j][q] = 0.f;

    // ---- tile loader (cp.async, 4 x 16B per thread) ----
    auto load_tile = [&](int buf, int kt) {
#pragma unroll
        for (int s = 0; s < 2; s++) {
            int chunk = tid + 256 * s;              // 0..511
            int row = chunk >> 2, kq = chunk & 3;   // A: 128 rows x 4 float4
            cp16(&As[buf][row * AS_STRIDE + kq * 4],
                 A + (size_t)(m0 + row) * NN + kt + kq * 4);
        }
#pragma unroll
        for (int s = 0; s < 2; s++) {
            int chunk = tid + 256 * s;
            int kr = chunk >> 5, nq = chunk & 31;   // B: 16 rows x 32 float4
            cp16(&Bs[buf][kr * BS_STRIDE + nq * 4],
                 B + (size_t)(kt + kr) * DD + nq * 4);
        }
        asm volatile("cp.async.commit_group;");
    };

    load_tile(0, k0);

    for (int it = 0; it < NT; it++) {
        int buf = it & 1;
        if (it + 1 < NT) {
            load_tile(buf ^ 1, k0 + (it + 1) * BK);
            asm volatile("cp.async.wait_group 1;");
        } else {
            asm volatile("cp.async.wait_group 0;");
        }
        __syncthreads();

#pragma unroll
        for (int ks = 0; ks < BK; ks += 8) {
            // A fragments (m16k8), tf32-converted
            unsigned ah[2][4];
#pragma unroll
            for (int t = 0; t < 2; t++) {
                int r = wm * 32 + t * 16 + (lane >> 2);
                int c = ks + (lane & 3);
                ah[t][0] = f2tf(As[buf][r * AS_STRIDE + c]);
                ah[t][1] = f2tf(As[buf][(r + 8) * AS_STRIDE + c]);
                ah[t][2] = f2tf(As[buf][r * AS_STRIDE + c + 4]);
                ah[t][3] = f2tf(As[buf][(r + 8) * AS_STRIDE + c + 4]);
            }
#pragma unroll
            for (int jb = 0; jb < 2; jb++) {
                unsigned bh[4][2];
#pragma unroll
                for (int jj = 0; jj < 4; jj++) {
                    int j = jb * 4 + jj;
                    int kk = ks + (lane & 3);
                    int n  = wn * 64 + j * 8 + (lane >> 2);
                    bh[jj][0] = f2tf(Bs[buf][kk * BS_STRIDE + n]);
                    bh[jj][1] = f2tf(Bs[buf][(kk + 4) * BS_STRIDE + n]);
                }
#pragma unroll
                for (int t = 0; t < 2; t++)
#pragma unroll
                    for (int jj = 0; jj < 4; jj++) {
                        mma8(acc[t][jb * 4 + jj], ah[t][0], ah[t][1], ah[t][2],
                             ah[t][3], bh[jj][0], bh[jj][1]);
                    }
            }
        }
        __syncthreads();
    }

    // ---- epilogue: split-K atomic accumulate (mode1 scales by 1/(norm+eps)) ----
#pragma unroll
    for (int t = 0; t < 2; t++) {
        int r0 = m0 + wm * 32 + t * 16 + (lane >> 2);
        float inv0 = 1.f, inv1 = 1.f;
        if (mode) {
            inv0 = 1.f / (g_norm[r0] + EPSF);
            inv1 = 1.f / (g_norm[r0 + 8] + EPSF);
        }
#pragma unroll
        for (int j = 0; j < 8; j++) {
            int cc = wn * 64 + j * 8 + (lane & 3) * 2;
            atomicAdd(&C[(size_t)r0 * DD + cc],           inv0 * acc[t][j][0]);
            atomicAdd(&C[(size_t)r0 * DD + cc + 1],       inv0 * acc[t][j][1]);
            atomicAdd(&C[(size_t)(r0 + 8) * DD + cc],     inv1 * acc[t][j][2]);
            atomicAdd(&C[(size_t)(r0 + 8) * DD + cc + 1], inv1 * acc[t][j][3]);
        }
    }
}

// ---------------------------------------------------------------------------
extern "C" void kernel_launch(void* const* d_in, const int* in_sizes, int n_in,
                              void* d_out, int out_size) {
    const void*  cur   = d_in[0];                 // currents (int64 or int32), [E]
    const void*  tgt   = d_in[1];                 // targets, [E]
    const float* act   = (const float*)d_in[2];   // activities_features [N, D]
    const float* cases = (const float*)d_in[3];   // cases_features [E, D]
    const float* W     = (const float*)d_in[4];   // W [N, N]
    float* out = (float*)d_out;                   // h [N, D]

    int E = in_sizes[3] / DD;                     // unambiguous regardless of index dtype

    // 0) zero scratch + dtype sniff
    k_zero<<<4096, 256>>>((const unsigned*)cur);
    // 1) edge scatter into dense att + row norms
    k_edge<<<(E + 7) / 8, 256>>>(cur, tgt, act, cases, E);
    // 2) feat = W @ activities (split-K accumulate into zeroed g_feat)
    k_gemm_tc<<<dim3(NN / BM, KS), 256>>>(W, act, out, 0);
    // 3) out = feat
    k_copy<<<512, 256>>>(out);
    // 4) out += (att @ feat) / (norm + eps)
    k_gemm_tc<<<dim3(NN / BM, KS), 256>>>(W, act, out, 1);
}

// round 12
// speedup vs baseline: 2.4873x; 1.0221x over previous
#include <cuda_runtime.h>
#include <cstdint>

#define NN 4096
#define DD 128
#define EPSF 1e-12f
#define KS 8            // split-K factor for GEMMs (256 CTAs -> 2/SM)
#define BM 128          // GEMM block rows
#define BK 16           // GEMM k-tile
#define AS_STRIDE 20    // floats; conflict-free for As[m][k] frag reads
#define BS_STRIDE 136   // floats; conflict-free for Bs[k][n] frag reads

// Scratch (static device allocation — no cudaMalloc allowed).
// RULE (cost of 3 failed rounds): __device__ symbols must NEVER be passed as
// kernel arguments from host code — host sees the shadow address, the kernel
// gets garbage, and the resulting illegal access poisons the whole graph.
// All symbol access happens inside device code.
__device__ __align__(256) float g_att[(size_t)NN * NN];  // 64 MB dense att input
__device__ __align__(256) float g_feat[NN * DD];         // W @ activities (raw fp32)
__device__ __align__(256) float g_Bcvt[NN * DD];         // current B, tf32-rounded
__device__ __align__(256) float g_norm[NN];              // row sums of g_att
__device__ int g_is64;                                   // index dtype sniff

// ---------------------------------------------------------------------------
// Kernel 0: zero att + feat + norm, sniff int64 vs int32 indices.
// ---------------------------------------------------------------------------
__global__ void k_zero(const unsigned* __restrict__ cur_raw) {
    if (blockIdx.x == 0 && threadIdx.x == 0) {
        unsigned o = 0;
#pragma unroll
        for (int i = 1; i < 128; i += 2) o |= cur_raw[i];
        g_is64 = (o == 0) ? 1 : 0;
    }
    size_t idx    = (size_t)blockIdx.x * blockDim.x + threadIdx.x;
    size_t stride = (size_t)gridDim.x * blockDim.x;
    float4 z = make_float4(0.f, 0.f, 0.f, 0.f);
    float4* pa = (float4*)g_att;
    const size_t na = ((size_t)NN * NN) / 4;
    for (size_t i = idx; i < na; i += stride) pa[i] = z;
    float4* pf = (float4*)g_feat;
    const size_t nf = (size_t)(NN * DD) / 4;
    for (size_t i = idx; i < nf; i += stride) pf[i] = z;
    for (size_t i = idx; i < NN; i += stride) g_norm[i] = 0.f;
}

// ---------------------------------------------------------------------------
// Kernel 1: one warp per edge. dist = ||h + case - t||, val = exp(-dist),
// scatter into att[t][c] and accumulate row norm (linear => == row sums).
// ---------------------------------------------------------------------------
__global__ void k_edge(const void* __restrict__ curp, const void* __restrict__ tgtp,
                       const float* __restrict__ act, const float* __restrict__ cases,
                       int E) {
    int w = (int)((blockIdx.x * blockDim.x + threadIdx.x) >> 5);
    if (w >= E) return;
    int lane = threadIdx.x & 31;
    int c, t;
    if (g_is64) {
        c = (int)((const long long*)curp)[w];
        t = (int)((const long long*)tgtp)[w];
    } else {
        c = ((const int*)curp)[w];
        t = ((const int*)tgtp)[w];
    }
    float4 hv = ((const float4*)act)[(size_t)c * (DD / 4) + lane];
    float4 tv = ((const float4*)act)[(size_t)t * (DD / 4) + lane];
    float4 cv = __ldcs(((const float4*)cases) + (size_t)w * (DD / 4) + lane);
    float dx = hv.x + cv.x - tv.x;
    float dy = hv.y + cv.y - tv.y;
    float dz = hv.z + cv.z - tv.z;
    float dw = hv.w + cv.w - tv.w;
    float s = dx * dx + dy * dy + dz * dz + dw * dw;
#pragma unroll
    for (int o = 16; o; o >>= 1) s += __shfl_xor_sync(0xffffffffu, s, o);
    if (lane == 0) {
        float v = __expf(-sqrtf(s));
        atomicAdd(&g_att[(size_t)t * NN + c], v);
        atomicAdd(&g_norm[t], v);
    }
}

// ---------------------------------------------------------------------------
// tf32 helpers
// ---------------------------------------------------------------------------
__device__ __forceinline__ unsigned f2tf(float x) {
    unsigned r;
    asm("cvt.rna.tf32.f32 %0, %1;" : "=r"(r) : "f"(x));
    return r;
}

// ---------------------------------------------------------------------------
// Kernel 2: elementwise tf32-round source -> g_Bcvt (SAME layout).
// Source selected DEVICE-SIDE: use_feat ? g_feat : Xin  (never pass a
// __device__ symbol from host!). Optionally writes source verbatim to outc
// (fuses the "out = feat" pre-init for GEMM2).
// ---------------------------------------------------------------------------
__global__ void k_prepB(const float* __restrict__ Xin, int use_feat,
                        float* __restrict__ outc) {
    const float* X = use_feat ? g_feat : Xin;
    int idx = blockIdx.x * blockDim.x + threadIdx.x;   // 0 .. 131071
    float4 v = ((const float4*)X)[idx];
    float4 r;
    r.x = __uint_as_float(f2tf(v.x));
    r.y = __uint_as_float(f2tf(v.y));
    r.z = __uint_as_float(f2tf(v.z));
    r.w = __uint_as_float(f2tf(v.w));
    ((float4*)g_Bcvt)[idx] = r;
    if (outc) ((float4*)outc)[idx] = v;
}

__device__ __forceinline__ void mma8(float* c, unsigned a0, unsigned a1,
                                     unsigned a2, unsigned a3,
                                     unsigned b0, unsigned b1) {
    asm volatile(
        "mma.sync.aligned.m16n8k8.row.col.f32.tf32.tf32.f32 "
        "{%0,%1,%2,%3}, {%4,%5,%6,%7}, {%8,%9}, {%0,%1,%2,%3};"
        : "+f"(c[0]), "+f"(c[1]), "+f"(c[2]), "+f"(c[3])
        : "r"(a0), "r"(a1), "r"(a2), "r"(a3), "r"(b0), "r"(b1));
}

__device__ __forceinline__ void cp16(float* smem_dst, const float* gmem_src) {
    unsigned sa = (unsigned)__cvta_generic_to_shared(smem_dst);
    asm volatile("cp.async.cg.shared.global [%0], [%1], 16;" :: "r"(sa), "l"(gmem_src));
}

// ---------------------------------------------------------------------------
// Kernel 4: tensor-core GEMM  C[4096,128] = A[4096,4096] @ B[4096,128]
// B is pre-rounded tf32 (g_Bcvt, identical layout) -> consumer reinterprets
// bits, no B cvt. A fragments keep cvt.rna (same numerics as the proven R8
// kernel). Per warp k-tile: 48 LDS + 16 cvt + 32 MMA (was 48+48+32).
// 8 warps (4 M x 2 N), warp tile 32x64, double-buffered cp.async, split-K=8.
//   mode 0: A=W,     B=g_Bcvt(=tf32(activities)), C=g_feat (zeroed)
//   mode 1: A=g_att, B=g_Bcvt(=tf32(feat)),       C=out (holds feat),
//           scaled by 1/(norm+eps)
// ---------------------------------------------------------------------------
__global__ void __launch_bounds__(256, 2)
k_gemm_tc(const float* __restrict__ Wp, float* __restrict__ outp, int mode) {
    __shared__ __align__(16) float As[2][BM * AS_STRIDE];  // 20480 B
    __shared__ __align__(16) float Bs[2][BK * BS_STRIDE];  // 17408 B

    const float* A = mode ? g_att : Wp;
    const float* B = g_Bcvt;
    float* C       = mode ? outp  : g_feat;

    const int tid  = threadIdx.x;
    const int lane = tid & 31;
    const int w    = tid >> 5;
    const int wm   = w & 3;      // warp row group (0..3) -> rows wm*32..+32
    const int wn   = w >> 2;     // warp col group (0..1) -> cols wn*64..+64
    const int m0   = blockIdx.x * BM;
    const int k0   = blockIdx.y * (NN / KS);
    const int NT   = (NN / KS) / BK;  // 32 k-tiles

    float acc[2][8][4];
#pragma unroll
    for (int t = 0; t < 2; t++)
#pragma unroll
        for (int j = 0; j < 8; j++)
#pragma unroll
            for (int q = 0; q < 4; q++) acc[t][j][q] = 0.f;

    // ---- tile loader (cp.async, 4 x 16B per thread) ----
    auto load_tile = [&](int buf, int kt) {
#pragma unroll
        for (int s = 0; s < 2; s++) {
            int chunk = tid + 256 * s;              // 0..511
            int row = chunk >> 2, kq = chunk & 3;   // A: 128 rows x 4 float4
            cp16(&As[buf][row * AS_STRIDE + kq * 4],
                 A + (size_t)(m0 + row) * NN + kt + kq * 4);
        }
#pragma unroll
        for (int s = 0; s < 2; s++) {
            int chunk = tid + 256 * s;
            int kr = chunk >> 5, nq = chunk & 31;   // B: 16 rows x 32 float4
            cp16(&Bs[buf][kr * BS_STRIDE + nq * 4],
                 B + (size_t)(kt + kr) * DD + nq * 4);
        }
        asm volatile("cp.async.commit_group;");
    };

    load_tile(0, k0);

    for (int it = 0; it < NT; it++) {
        int buf = it & 1;
        if (it + 1 < NT) {
            load_tile(buf ^ 1, k0 + (it + 1) * BK);
            asm volatile("cp.async.wait_group 1;");
        } else {
            asm volatile("cp.async.wait_group 0;");
        }
        __syncthreads();

#pragma unroll
        for (int ks = 0; ks < BK; ks += 8) {
            // A fragments (m16k8), tf32-converted (rna — same as R8)
            unsigned ah[2][4];
#pragma unroll
            for (int t = 0; t < 2; t++) {
                int r = wm * 32 + t * 16 + (lane >> 2);
                int c = ks + (lane & 3);
                ah[t][0] = f2tf(As[buf][r * AS_STRIDE + c]);
                ah[t][1] = f2tf(As[buf][(r + 8) * AS_STRIDE + c]);
                ah[t][2] = f2tf(As[buf][r * AS_STRIDE + c + 4]);
                ah[t][3] = f2tf(As[buf][(r + 8) * AS_STRIDE + c + 4]);
            }
#pragma unroll
            for (int jb = 0; jb < 2; jb++) {
                unsigned bh[4][2];
#pragma unroll
                for (int jj = 0; jj < 4; jj++) {
                    int j = jb * 4 + jj;
                    int kk = ks + (lane & 3);
                    int n  = wn * 64 + j * 8 + (lane >> 2);
                    bh[jj][0] = __float_as_uint(Bs[buf][kk * BS_STRIDE + n]);
                    bh[jj][1] = __float_as_uint(Bs[buf][(kk + 4) * BS_STRIDE + n]);
                }
#pragma unroll
                for (int t = 0; t < 2; t++)
#pragma unroll
                    for (int jj = 0; jj < 4; jj++) {
                        mma8(acc[t][jb * 4 + jj], ah[t][0], ah[t][1], ah[t][2],
                             ah[t][3], bh[jj][0], bh[jj][1]);
                    }
            }
        }
        __syncthreads();
    }

    // ---- epilogue: split-K atomic accumulate (mode1 scales by 1/(norm+eps)) ----
#pragma unroll
    for (int t = 0; t < 2; t++) {
        int r0 = m0 + wm * 32 + t * 16 + (lane >> 2);
        float inv0 = 1.f, inv1 = 1.f;
        if (mode) {
            inv0 = 1.f / (g_norm[r0] + EPSF);
            inv1 = 1.f / (g_norm[r0 + 8] + EPSF);
        }
#pragma unroll
        for (int j = 0; j < 8; j++) {
            int cc = wn * 64 + j * 8 + (lane & 3) * 2;
            atomicAdd(&C[(size_t)r0 * DD + cc],           inv0 * acc[t][j][0]);
            atomicAdd(&C[(size_t)r0 * DD + cc + 1],       inv0 * acc[t][j][1]);
            atomicAdd(&C[(size_t)(r0 + 8) * DD + cc],     inv1 * acc[t][j][2]);
            atomicAdd(&C[(size_t)(r0 + 8) * DD + cc + 1], inv1 * acc[t][j][3]);
        }
    }
}

// ---------------------------------------------------------------------------
extern "C" void kernel_launch(void* const* d_in, const int* in_sizes, int n_in,
                              void* d_out, int out_size) {
    const void*  cur   = d_in[0];                 // currents (int64 or int32), [E]
    const void*  tgt   = d_in[1];                 // targets, [E]
    const float* act   = (const float*)d_in[2];   // activities_features [N, D]
    const float* cases = (const float*)d_in[3];   // cases_features [E, D]
    const float* W     = (const float*)d_in[4];   // W [N, N]
    float* out = (float*)d_out;                   // h [N, D]

    int E = in_sizes[3] / DD;                     // unambiguous regardless of index dtype

    // 0) zero scratch + dtype sniff
    k_zero<<<4096, 256>>>((const unsigned*)cur);
    // 1) g_Bcvt = tf32(activities)   (source = harness ptr, flag 0)
    k_prepB<<<512, 256>>>(act, 0, nullptr);
    // 2) edge scatter into dense att + row norms
    k_edge<<<(E + 7) / 8, 256>>>(cur, tgt, act, cases, E);
    // 3) feat = W @ activities (split-K accumulate into zeroed g_feat)
    k_gemm_tc<<<dim3(NN / BM, KS), 256>>>(W, out, 0);
    // 4) g_Bcvt = tf32(feat) and out = feat  (source = g_feat via FLAG, not
    //    a host-passed symbol — that was the bug that killed R6/R7/R11)
    k_prepB<<<512, 256>>>(nullptr, 1, out);
    // 5) out += (att @ feat) / (norm + eps)
    k_gemm_tc<<<dim3(NN / BM, KS), 256>>>(W, out, 1);
}